// round 4
// baseline (speedup 1.0000x reference)
#include <cuda_runtime.h>
#include <cstring>

#define BB     16
#define CC     512
#define SS     1024
#define HEADS  8
#define DH     64
#define INNER  512     // HEADS*DH
#define N3     1536    // 3*INNER
#define ATT_SCALE 0.125f  // 64^-0.5

// Scratch (static device globals — allocation-free per harness rules)
__device__ float g_qkv[(size_t)BB * SS * N3];    // [b][s][h*192 + {q,k,v}]
__device__ float g_res[(size_t)BB * SS * INNER]; // [b][s][h*64+d]

typedef unsigned long long ull;

__device__ __forceinline__ void ffma2(ull& d, ull a, ull b) {
    asm("fma.rn.f32x2 %0, %1, %2, %0;" : "+l"(d) : "l"(a), "l"(b));
}
__device__ __forceinline__ float2 u2f(ull u) {
    float2 f; memcpy(&f, &u, 8); return f;
}

// Dynamic smem layout for GEMMs:
//   sA2: 2 buf x 16 k x 264 (A duplicated: [2m]=[2m+1]=a[m]); 8448 floats
//   sB : 2 buf x 16 k x 132;                                  4224 floats
#define GEMM_SMEM_BYTES ((8448 + 4224) * 4)

// ---------------------------------------------------------------------------
// Kernel 1: qkv = xs @ W_proj + b_proj, xs[b][s][c] = x[b][c][s]
// 128x128 tile, 8 rows x 4 col-pairs per thread via fma.rn.f32x2.
// ---------------------------------------------------------------------------
__global__ __launch_bounds__(256, 2) void qkv_gemm_k(
    const float* __restrict__ x, const float* __restrict__ Wp,
    const float* __restrict__ bp)
{
    extern __shared__ float dynsm[];
    float* sA2 = dynsm;            // [buf][k][264]
    float* sB  = dynsm + 8448;     // [buf][k][132]

    const int n0 = blockIdx.x * 128;
    const int m0 = blockIdx.y * 128;
    const int b  = m0 >> 10;
    const int s0 = m0 & (SS - 1);
    const int tid = threadIdx.x;
    const int tx = tid & 15, ty = tid >> 4;
    const int lk = tid >> 4, lt = tid & 15;  // loader: row lk, col-group lt

    // prologue: load k0=0 into buf 0
    float4 av0, av1, bv0, bv1;
    {
        const size_t arow = ((size_t)(b * CC + lk)) * SS + s0 + lt * 4;
        const size_t brow = (size_t)lk * N3 + n0 + lt * 4;
        av0 = *(const float4*)&x[arow];
        av1 = *(const float4*)&x[arow + 64];
        bv0 = *(const float4*)&Wp[brow];
        bv1 = *(const float4*)&Wp[brow + 64];
    }
    {
        float* A = &sA2[(0 * 16 + lk) * 264];
        *(float4*)&A[8 * lt]           = make_float4(av0.x, av0.x, av0.y, av0.y);
        *(float4*)&A[8 * lt + 4]       = make_float4(av0.z, av0.z, av0.w, av0.w);
        *(float4*)&A[128 + 8 * lt]     = make_float4(av1.x, av1.x, av1.y, av1.y);
        *(float4*)&A[128 + 8 * lt + 4] = make_float4(av1.z, av1.z, av1.w, av1.w);
        float* Bx = &sB[(0 * 16 + lk) * 132];
        *(float4*)&Bx[4 * lt]      = bv0;
        *(float4*)&Bx[64 + 4 * lt] = bv1;
    }
    __syncthreads();

    ull acc2[8][4];
    #pragma unroll
    for (int r = 0; r < 8; r++)
        #pragma unroll
        for (int p = 0; p < 4; p++) acc2[r][p] = 0ull;

    for (int k0 = 0; k0 < CC; k0 += 16) {
        const int buf = (k0 >> 4) & 1;
        const bool more = (k0 + 16) < CC;
        if (more) {
            const size_t arow = ((size_t)(b * CC + k0 + 16 + lk)) * SS + s0 + lt * 4;
            const size_t brow = (size_t)(k0 + 16 + lk) * N3 + n0 + lt * 4;
            av0 = *(const float4*)&x[arow];
            av1 = *(const float4*)&x[arow + 64];
            bv0 = *(const float4*)&Wp[brow];
            bv1 = *(const float4*)&Wp[brow + 64];
        }
        #pragma unroll
        for (int k = 0; k < 16; k++) {
            const float* A = &sA2[(buf * 16 + k) * 264];
            const float* Bx = &sB[(buf * 16 + k) * 132];
            ulonglong2 q0 = *(const ulonglong2*)&A[8 * ty];
            ulonglong2 q1 = *(const ulonglong2*)&A[8 * ty + 4];
            ulonglong2 q2 = *(const ulonglong2*)&A[128 + 8 * ty];
            ulonglong2 q3 = *(const ulonglong2*)&A[128 + 8 * ty + 4];
            ulonglong2 b0 = *(const ulonglong2*)&Bx[4 * tx];
            ulonglong2 b1 = *(const ulonglong2*)&Bx[64 + 4 * tx];
            ull a2[8] = {q0.x, q0.y, q1.x, q1.y, q2.x, q2.y, q3.x, q3.y};
            ull bp2[4] = {b0.x, b0.y, b1.x, b1.y};
            #pragma unroll
            for (int r = 0; r < 8; r++)
                #pragma unroll
                for (int p = 0; p < 4; p++)
                    ffma2(acc2[r][p], a2[r], bp2[p]);
        }
        if (more) {
            const int nb = buf ^ 1;
            float* A = &sA2[(nb * 16 + lk) * 264];
            *(float4*)&A[8 * lt]           = make_float4(av0.x, av0.x, av0.y, av0.y);
            *(float4*)&A[8 * lt + 4]       = make_float4(av0.z, av0.z, av0.w, av0.w);
            *(float4*)&A[128 + 8 * lt]     = make_float4(av1.x, av1.x, av1.y, av1.y);
            *(float4*)&A[128 + 8 * lt + 4] = make_float4(av1.z, av1.z, av1.w, av1.w);
            float* Bx = &sB[(nb * 16 + lk) * 132];
            *(float4*)&Bx[4 * lt]      = bv0;
            *(float4*)&Bx[64 + 4 * lt] = bv1;
            __syncthreads();
        }
    }

    const float4 bias0 = *(const float4*)&bp[n0 + tx * 4];
    const float4 bias1 = *(const float4*)&bp[n0 + 64 + tx * 4];
    #pragma unroll
    for (int r = 0; r < 8; r++) {
        const int row = m0 + ((r < 4) ? (ty * 4 + r) : (64 + ty * 4 + r - 4));
        float* dst = &g_qkv[(size_t)row * N3 + n0 + tx * 4];
        float2 f0 = u2f(acc2[r][0]), f1 = u2f(acc2[r][1]);
        float2 f2 = u2f(acc2[r][2]), f3 = u2f(acc2[r][3]);
        float4 o0 = make_float4(f0.x + bias0.x, f0.y + bias0.y,
                                f1.x + bias0.z, f1.y + bias0.w);
        float4 o1 = make_float4(f2.x + bias1.x, f2.y + bias1.y,
                                f3.x + bias1.z, f3.y + bias1.w);
        *(float4*)dst = o0;
        *(float4*)(dst + 64) = o1;
    }
}

// ---------------------------------------------------------------------------
// Kernel 2: flash attention per (b,h,q-tile). 128 q x 64-key tiles.
// Scale folded into Q; next K/V tile prefetched into registers.
// ---------------------------------------------------------------------------
__global__ __launch_bounds__(256, 2) void attn_k()
{
    extern __shared__ float sm[];
    float* sQ = sm;                 // 128 x 65
    float* sK = sQ + 128 * 65;      // 64 x 65
    float* sV = sK + 64 * 65;       // 64 x 65
    float* sP = sV + 64 * 65;       // 128 x 65

    const int bh = blockIdx.y;
    const int b = bh >> 3, h = bh & 7;
    const int q0 = blockIdx.x * 128;
    const int tid = threadIdx.x;
    const int tx = tid & 15, ty = tid >> 4;

    const float* qbase = g_qkv + (size_t)b * SS * N3 + h * (3 * DH);

    // Load Q tile (scaled)
    #pragma unroll
    for (int it = 0; it < 8; it++) {
        int idx = tid + it * 256;
        int i = idx >> 4, d4 = (idx & 15) << 2;
        float4 v = *(const float4*)&qbase[(size_t)(q0 + i) * N3 + d4];
        float* p = &sQ[i * 65 + d4];
        p[0] = v.x * ATT_SCALE; p[1] = v.y * ATT_SCALE;
        p[2] = v.z * ATT_SCALE; p[3] = v.w * ATT_SCALE;
    }

    float m_i[8], l_i[8], o[8][4] = {};
    #pragma unroll
    for (int r = 0; r < 8; r++) { m_i[r] = -1e30f; l_i[r] = 0.f; }

    // Prefetch kt=0 K/V
    float4 kreg[4], vreg[4];
    #pragma unroll
    for (int it = 0; it < 4; it++) {
        int idx = tid + it * 256;
        int j = idx >> 4, d4 = (idx & 15) << 2;
        const float* row = &qbase[(size_t)j * N3];
        kreg[it] = *(const float4*)&row[DH + d4];
        vreg[it] = *(const float4*)&row[2 * DH + d4];
    }

    for (int kt = 0; kt < 16; kt++) {
        __syncthreads();   // prev PV reads of sK/sV done (and Q store for kt=0)
        #pragma unroll
        for (int it = 0; it < 4; it++) {
            int idx = tid + it * 256;
            int j = idx >> 4, d4 = (idx & 15) << 2;
            float* pk = &sK[j * 65 + d4];
            float* pv = &sV[j * 65 + d4];
            pk[0] = kreg[it].x; pk[1] = kreg[it].y; pk[2] = kreg[it].z; pk[3] = kreg[it].w;
            pv[0] = vreg[it].x; pv[1] = vreg[it].y; pv[2] = vreg[it].z; pv[3] = vreg[it].w;
        }
        __syncthreads();
        if (kt + 1 < 16) {
            const int k0n = (kt + 1) * 64;
            #pragma unroll
            for (int it = 0; it < 4; it++) {
                int idx = tid + it * 256;
                int j = idx >> 4, d4 = (idx & 15) << 2;
                const float* row = &qbase[(size_t)(k0n + j) * N3];
                kreg[it] = *(const float4*)&row[DH + d4];
                vreg[it] = *(const float4*)&row[2 * DH + d4];
            }
        }

        // S = Q K^T
        float sf[8][4] = {};
        #pragma unroll 8
        for (int d = 0; d < 64; d++) {
            float a[8], bq[4];
            #pragma unroll
            for (int r = 0; r < 4; r++) {
                a[r]     = sQ[(ty * 4 + r) * 65 + d];
                a[r + 4] = sQ[(64 + ty * 4 + r) * 65 + d];
            }
            #pragma unroll
            for (int c = 0; c < 4; c++) bq[c] = sK[(tx * 4 + c) * 65 + d];
            #pragma unroll
            for (int r = 0; r < 8; r++)
                #pragma unroll
                for (int c = 0; c < 4; c++)
                    sf[r][c] = fmaf(a[r], bq[c], sf[r][c]);
        }

        // Online softmax per owned row
        #pragma unroll
        for (int r = 0; r < 8; r++) {
            const int qrow = (r < 4) ? (ty * 4 + r) : (64 + ty * 4 + r - 4);
            float mx = fmaxf(fmaxf(sf[r][0], sf[r][1]), fmaxf(sf[r][2], sf[r][3]));
            #pragma unroll
            for (int off = 8; off >= 1; off >>= 1)
                mx = fmaxf(mx, __shfl_xor_sync(0xffffffffu, mx, off));
            float m_new = fmaxf(m_i[r], mx);
            float rs = 0.f;
            #pragma unroll
            for (int c = 0; c < 4; c++) {
                float p = __expf(sf[r][c] - m_new);
                rs += p;
                sP[qrow * 65 + tx * 4 + c] = p;
            }
            #pragma unroll
            for (int off = 8; off >= 1; off >>= 1)
                rs += __shfl_xor_sync(0xffffffffu, rs, off);
            float alpha = __expf(m_i[r] - m_new);
            l_i[r] = l_i[r] * alpha + rs;
            m_i[r] = m_new;
            #pragma unroll
            for (int c = 0; c < 4; c++) o[r][c] *= alpha;
        }
        __syncwarp();

        // O += P V
        #pragma unroll 8
        for (int j = 0; j < 64; j++) {
            float a[8], bq[4];
            #pragma unroll
            for (int r = 0; r < 4; r++) {
                a[r]     = sP[(ty * 4 + r) * 65 + j];
                a[r + 4] = sP[(64 + ty * 4 + r) * 65 + j];
            }
            #pragma unroll
            for (int c = 0; c < 4; c++) bq[c] = sV[j * 65 + tx * 4 + c];
            #pragma unroll
            for (int r = 0; r < 8; r++)
                #pragma unroll
                for (int c = 0; c < 4; c++)
                    o[r][c] = fmaf(a[r], bq[c], o[r][c]);
        }
    }

    float* rbase = g_res + ((size_t)b * SS + q0) * INNER + h * DH;
    #pragma unroll
    for (int r = 0; r < 8; r++) {
        const int qrow = (r < 4) ? (ty * 4 + r) : (64 + ty * 4 + r - 4);
        float inv = 1.f / l_i[r];
        float4 ov;
        ov.x = o[r][0] * inv; ov.y = o[r][1] * inv;
        ov.z = o[r][2] * inv; ov.w = o[r][3] * inv;
        *(float4*)&rbase[(size_t)qrow * INNER + tx * 4] = ov;
    }
}

// ---------------------------------------------------------------------------
// Kernel 3: out[b][c][s] = res @ W_out + b_out + x, f32x2 + double buffer.
// Rows r = c-dim (from dup'd W_out tile), cols = s-dim (pairs).
// ---------------------------------------------------------------------------
__global__ __launch_bounds__(256, 2) void out_gemm_k(
    const float* __restrict__ x, const float* __restrict__ Wo,
    const float* __restrict__ bo, float* __restrict__ out)
{
    extern __shared__ float dynsm[];
    float* sA2 = dynsm;            // [buf][k][264]  dup'd W_out
    float* sB  = dynsm + 8448;     // [buf][k][132]  res transposed

    const int s0 = blockIdx.x * 128;
    const int c0 = blockIdx.y * 128;
    const int b  = blockIdx.z;
    const int tid = threadIdx.x;
    const int tx = tid & 15, ty = tid >> 4;
    const int lk = tid >> 4, lt = tid & 15;
    const int ls = tid >> 1, lkb = (tid & 1) << 3;

    float4 av0, av1, bv0, bv1;
    {
        const size_t arow = (size_t)lk * CC + c0 + lt * 4;
        av0 = *(const float4*)&Wo[arow];
        av1 = *(const float4*)&Wo[arow + 64];
        const size_t brow = ((size_t)(b * SS + s0 + ls)) * INNER + lkb;
        bv0 = *(const float4*)&g_res[brow];
        bv1 = *(const float4*)&g_res[brow + 4];
    }
    {
        float* A = &sA2[(0 * 16 + lk) * 264];
        *(float4*)&A[8 * lt]           = make_float4(av0.x, av0.x, av0.y, av0.y);
        *(float4*)&A[8 * lt + 4]       = make_float4(av0.z, av0.z, av0.w, av0.w);
        *(float4*)&A[128 + 8 * lt]     = make_float4(av1.x, av1.x, av1.y, av1.y);
        *(float4*)&A[128 + 8 * lt + 4] = make_float4(av1.z, av1.z, av1.w, av1.w);
        float* Bb = &sB[0];
        Bb[(lkb + 0) * 132 + ls] = bv0.x; Bb[(lkb + 1) * 132 + ls] = bv0.y;
        Bb[(lkb + 2) * 132 + ls] = bv0.z; Bb[(lkb + 3) * 132 + ls] = bv0.w;
        Bb[(lkb + 4) * 132 + ls] = bv1.x; Bb[(lkb + 5) * 132 + ls] = bv1.y;
        Bb[(lkb + 6) * 132 + ls] = bv1.z; Bb[(lkb + 7) * 132 + ls] = bv1.w;
    }
    __syncthreads();

    ull acc2[8][4];
    #pragma unroll
    for (int r = 0; r < 8; r++)
        #pragma unroll
        for (int p = 0; p < 4; p++) acc2[r][p] = 0ull;

    for (int k0 = 0; k0 < INNER; k0 += 16) {
        const int buf = (k0 >> 4) & 1;
        const bool more = (k0 + 16) < INNER;
        if (more) {
            const size_t arow = (size_t)(k0 + 16 + lk) * CC + c0 + lt * 4;
            av0 = *(const float4*)&Wo[arow];
            av1 = *(const float4*)&Wo[arow + 64];
            const size_t brow = ((size_t)(b * SS + s0 + ls)) * INNER + k0 + 16 + lkb;
            bv0 = *(const float4*)&g_res[brow];
            bv1 = *(const float4*)&g_res[brow + 4];
        }
        #pragma unroll
        for (int k = 0; k < 16; k++) {
            const float* A = &sA2[(buf * 16 + k) * 264];
            const float* Bx = &sB[(buf * 16 + k) * 132];
            ulonglong2 q0 = *(const ulonglong2*)&A[8 * ty];
            ulonglong2 q1 = *(const ulonglong2*)&A[8 * ty + 4];
            ulonglong2 q2 = *(const ulonglong2*)&A[128 + 8 * ty];
            ulonglong2 q3 = *(const ulonglong2*)&A[128 + 8 * ty + 4];
            ulonglong2 b0 = *(const ulonglong2*)&Bx[4 * tx];
            ulonglong2 b1 = *(const ulonglong2*)&Bx[64 + 4 * tx];
            ull a2[8] = {q0.x, q0.y, q1.x, q1.y, q2.x, q2.y, q3.x, q3.y};
            ull bp2[4] = {b0.x, b0.y, b1.x, b1.y};
            #pragma unroll
            for (int r = 0; r < 8; r++)
                #pragma unroll
                for (int p = 0; p < 4; p++)
                    ffma2(acc2[r][p], a2[r], bp2[p]);
        }
        if (more) {
            const int nb = buf ^ 1;
            float* A = &sA2[(nb * 16 + lk) * 264];
            *(float4*)&A[8 * lt]           = make_float4(av0.x, av0.x, av0.y, av0.y);
            *(float4*)&A[8 * lt + 4]       = make_float4(av0.z, av0.z, av0.w, av0.w);
            *(float4*)&A[128 + 8 * lt]     = make_float4(av1.x, av1.x, av1.y, av1.y);
            *(float4*)&A[128 + 8 * lt + 4] = make_float4(av1.z, av1.z, av1.w, av1.w);
            float* Bb = &sB[nb * 16 * 132];
            Bb[(lkb + 0) * 132 + ls] = bv0.x; Bb[(lkb + 1) * 132 + ls] = bv0.y;
            Bb[(lkb + 2) * 132 + ls] = bv0.z; Bb[(lkb + 3) * 132 + ls] = bv0.w;
            Bb[(lkb + 4) * 132 + ls] = bv1.x; Bb[(lkb + 5) * 132 + ls] = bv1.y;
            Bb[(lkb + 6) * 132 + ls] = bv1.z; Bb[(lkb + 7) * 132 + ls] = bv1.w;
            __syncthreads();
        }
    }

    #pragma unroll
    for (int r = 0; r < 8; r++) {
        const int c = c0 + ((r < 4) ? (ty * 4 + r) : (64 + ty * 4 + r - 4));
        const float bias = bo[c];
        const size_t base = ((size_t)(b * CC + c)) * SS + s0 + tx * 4;
        float4 xv0 = *(const float4*)&x[base];
        float4 xv1 = *(const float4*)&x[base + 64];
        float2 f0 = u2f(acc2[r][0]), f1 = u2f(acc2[r][1]);
        float2 f2 = u2f(acc2[r][2]), f3 = u2f(acc2[r][3]);
        float4 o0 = make_float4(f0.x + bias + xv0.x, f0.y + bias + xv0.y,
                                f1.x + bias + xv0.z, f1.y + bias + xv0.w);
        float4 o1 = make_float4(f2.x + bias + xv1.x, f2.y + bias + xv1.y,
                                f3.x + bias + xv1.z, f3.y + bias + xv1.w);
        *(float4*)&out[base] = o0;
        *(float4*)&out[base + 64] = o1;
    }
}

// ---------------------------------------------------------------------------
extern "C" void kernel_launch(void* const* d_in, const int* in_sizes, int n_in,
                              void* d_out, int out_size)
{
    const float* x  = (const float*)d_in[0];
    const float* Wp = (const float*)d_in[1];
    const float* bp = (const float*)d_in[2];
    const float* Wo = (const float*)d_in[3];
    const float* bo = (const float*)d_in[4];
    float* out = (float*)d_out;

    const int attn_smem = (128 + 64 + 64 + 128) * 65 * (int)sizeof(float); // 99840
    cudaFuncSetAttribute(attn_k, cudaFuncAttributeMaxDynamicSharedMemorySize,
                         attn_smem);
    cudaFuncSetAttribute(qkv_gemm_k, cudaFuncAttributeMaxDynamicSharedMemorySize,
                         GEMM_SMEM_BYTES);
    cudaFuncSetAttribute(out_gemm_k, cudaFuncAttributeMaxDynamicSharedMemorySize,
                         GEMM_SMEM_BYTES);

    dim3 g1(N3 / 128, (BB * SS) / 128);        // 12 x 128
    qkv_gemm_k<<<g1, 256, GEMM_SMEM_BYTES>>>(x, Wp, bp);

    dim3 g2(SS / 128, BB * HEADS);             // 8 x 128
    attn_k<<<g2, 256, attn_smem>>>();

    dim3 g3(SS / 128, CC / 128, BB);           // 8 x 4 x 16
    out_gemm_k<<<g3, 256, GEMM_SMEM_BYTES>>>(x, Wo, bo, out);
}

// round 5
// speedup vs baseline: 1.1715x; 1.1715x over previous
#include <cuda_runtime.h>

#define BB     16
#define CC     512
#define SS     1024
#define HEADS  8
#define DH     64
#define INNER  512     // HEADS*DH
#define N3     1536    // 3*INNER
#define ATT_SCALE 0.125f  // 64^-0.5

// Scratch (static device globals — allocation-free per harness rules)
__device__ float g_qkv[(size_t)BB * SS * N3];    // [b][s][h*192 + {q,k,v}]
__device__ float g_res[(size_t)BB * SS * INNER]; // [b][s][h*64+d]

// ---------------------------------------------------------------------------
// Kernel 1: qkv = xs @ W_proj + b_proj, xs[b][s][c] = x[b][c][s]
// 128x128 tile, 8x8 frag, Kstep=16, double-buffered smem.
// ---------------------------------------------------------------------------
__global__ __launch_bounds__(256, 2) void qkv_gemm_k(
    const float* __restrict__ x, const float* __restrict__ Wp,
    const float* __restrict__ bp)
{
    __shared__ float sA[2][16][132];   // [buf][k][m]
    __shared__ float sB[2][16][132];   // [buf][k][n]
    const int n0 = blockIdx.x * 128;
    const int m0 = blockIdx.y * 128;
    const int b  = m0 >> 10;
    const int s0 = m0 & (SS - 1);
    const int tid = threadIdx.x;
    const int tx = tid & 15, ty = tid >> 4;
    const int lk = tid >> 4, lm4 = (tid & 15) << 2;

    float4 av0, av1, bv0, bv1;
    {
        const size_t arow = ((size_t)(b * CC + lk)) * SS + s0 + lm4;
        const size_t brow = (size_t)lk * N3 + n0 + lm4;
        av0 = *(const float4*)&x[arow];
        av1 = *(const float4*)&x[arow + 64];
        bv0 = *(const float4*)&Wp[brow];
        bv1 = *(const float4*)&Wp[brow + 64];
    }
    *(float4*)&sA[0][lk][lm4]      = av0;
    *(float4*)&sA[0][lk][lm4 + 64] = av1;
    *(float4*)&sB[0][lk][lm4]      = bv0;
    *(float4*)&sB[0][lk][lm4 + 64] = bv1;
    __syncthreads();

    float acc[8][8] = {};
    for (int k0 = 0; k0 < CC; k0 += 16) {
        const int buf = (k0 >> 4) & 1;
        const bool more = (k0 + 16) < CC;
        if (more) {
            const size_t arow = ((size_t)(b * CC + k0 + 16 + lk)) * SS + s0 + lm4;
            const size_t brow = (size_t)(k0 + 16 + lk) * N3 + n0 + lm4;
            av0 = *(const float4*)&x[arow];
            av1 = *(const float4*)&x[arow + 64];
            bv0 = *(const float4*)&Wp[brow];
            bv1 = *(const float4*)&Wp[brow + 64];
        }
        #pragma unroll
        for (int k = 0; k < 16; k++) {
            float a[8], bq[8];
            #pragma unroll
            for (int r = 0; r < 4; r++) {
                a[r]      = sA[buf][k][ty * 4 + r];
                a[r + 4]  = sA[buf][k][64 + ty * 4 + r];
                bq[r]     = sB[buf][k][tx * 4 + r];
                bq[r + 4] = sB[buf][k][64 + tx * 4 + r];
            }
            #pragma unroll
            for (int r = 0; r < 8; r++)
                #pragma unroll
                for (int c = 0; c < 8; c++)
                    acc[r][c] = fmaf(a[r], bq[c], acc[r][c]);
        }
        if (more) {
            const int nb = buf ^ 1;
            *(float4*)&sA[nb][lk][lm4]      = av0;
            *(float4*)&sA[nb][lk][lm4 + 64] = av1;
            *(float4*)&sB[nb][lk][lm4]      = bv0;
            *(float4*)&sB[nb][lk][lm4 + 64] = bv1;
            __syncthreads();
        }
    }

    const float4 bias0 = *(const float4*)&bp[n0 + tx * 4];
    const float4 bias1 = *(const float4*)&bp[n0 + 64 + tx * 4];
    #pragma unroll
    for (int r = 0; r < 8; r++) {
        const int row = m0 + ((r < 4) ? (ty * 4 + r) : (64 + ty * 4 + r - 4));
        float* dst = &g_qkv[(size_t)row * N3 + n0 + tx * 4];
        float4 o0, o1;
        o0.x = acc[r][0] + bias0.x; o0.y = acc[r][1] + bias0.y;
        o0.z = acc[r][2] + bias0.z; o0.w = acc[r][3] + bias0.w;
        o1.x = acc[r][4] + bias1.x; o1.y = acc[r][5] + bias1.y;
        o1.z = acc[r][6] + bias1.z; o1.w = acc[r][7] + bias1.w;
        *(float4*)dst = o0;
        *(float4*)(dst + 64) = o1;
    }
}

// ---------------------------------------------------------------------------
// Kernel 2: flash attention, 128 q x 64-key tiles, transposed Q/K in smem
// (XOR-swizzled), vectorized P/V. 256 threads, 16x16, 8x4 frags.
// ---------------------------------------------------------------------------
__global__ __launch_bounds__(256, 2) void attn_k()
{
    extern __shared__ float sm[];
    float* sQt = sm;                  // [64][128] Q^T (scaled, swizzled)
    float* sKt = sQt + 64 * 128;      // [64][64]  K^T (swizzled)
    float* sV  = sKt + 64 * 64;       // [64][68]
    float* sP  = sV + 64 * 68;        // [128][68]
    float4* sQtv = (float4*)sQt;      // row stride 32
    float4* sKtv = (float4*)sKt;      // row stride 16
    float4* sVv  = (float4*)sV;       // row stride 17
    float4* sPv  = (float4*)sP;       // row stride 17

    const int bh = blockIdx.y;
    const int b = bh >> 3, h = bh & 7;
    const int q0 = blockIdx.x * 128;
    const int tid = threadIdx.x;
    const int tx = tid & 15, ty = tid >> 4;

    const float* qbase = g_qkv + (size_t)b * SS * N3 + h * (3 * DH);

    // ---- Q^T: micro-transpose 4x4 per work item, 2 items per thread ----
    #pragma unroll
    for (int it = 0; it < 2; it++) {
        int idx = tid + it * 256;
        int d4g = idx & 15, rg = idx >> 4;       // rg 0..31
        int d4 = d4g << 2, i0 = rg << 2;
        float4 m0 = *(const float4*)&qbase[(size_t)(q0 + i0 + 0) * N3 + d4];
        float4 m1 = *(const float4*)&qbase[(size_t)(q0 + i0 + 1) * N3 + d4];
        float4 m2 = *(const float4*)&qbase[(size_t)(q0 + i0 + 2) * N3 + d4];
        float4 m3 = *(const float4*)&qbase[(size_t)(q0 + i0 + 3) * N3 + d4];
        int phys = (rg & 16) | ((rg & 15) ^ d4g);
        sQtv[(d4 + 0) * 32 + phys] = make_float4(m0.x * ATT_SCALE, m1.x * ATT_SCALE,
                                                 m2.x * ATT_SCALE, m3.x * ATT_SCALE);
        sQtv[(d4 + 1) * 32 + phys] = make_float4(m0.y * ATT_SCALE, m1.y * ATT_SCALE,
                                                 m2.y * ATT_SCALE, m3.y * ATT_SCALE);
        sQtv[(d4 + 2) * 32 + phys] = make_float4(m0.z * ATT_SCALE, m1.z * ATT_SCALE,
                                                 m2.z * ATT_SCALE, m3.z * ATT_SCALE);
        sQtv[(d4 + 3) * 32 + phys] = make_float4(m0.w * ATT_SCALE, m1.w * ATT_SCALE,
                                                 m2.w * ATT_SCALE, m3.w * ATT_SCALE);
    }

    float m_i[8], l_i[8], o[8][4] = {};
    #pragma unroll
    for (int r = 0; r < 8; r++) { m_i[r] = -1e30f; l_i[r] = 0.f; }

    const int kd4g = tid & 15, krg = tid >> 4;   // K loader coords
    const int kd4 = kd4g << 2, kj0 = krg << 2;
    const int kphys = krg ^ kd4g;

    // Prefetch kt=0 K (V prefetched after softmax each iteration)
    float4 kreg[4], vreg[4];
    #pragma unroll
    for (int r = 0; r < 4; r++)
        kreg[r] = *(const float4*)&qbase[(size_t)(kj0 + r) * N3 + DH + kd4];
    #pragma unroll
    for (int it = 0; it < 4; it++) {
        int idx = tid + it * 256;
        int j = idx >> 4, c4 = (idx & 15) << 2;
        vreg[it] = *(const float4*)&qbase[(size_t)j * N3 + 2 * DH + c4];
    }

    for (int kt = 0; kt < 16; kt++) {
        __syncthreads();   // prior tile's reads of sKt/sV done (and Q store @kt0)
        // store K^T (swizzled) and V
        sKtv[(kd4 + 0) * 16 + kphys] = make_float4(kreg[0].x, kreg[1].x, kreg[2].x, kreg[3].x);
        sKtv[(kd4 + 1) * 16 + kphys] = make_float4(kreg[0].y, kreg[1].y, kreg[2].y, kreg[3].y);
        sKtv[(kd4 + 2) * 16 + kphys] = make_float4(kreg[0].z, kreg[1].z, kreg[2].z, kreg[3].z);
        sKtv[(kd4 + 3) * 16 + kphys] = make_float4(kreg[0].w, kreg[1].w, kreg[2].w, kreg[3].w);
        #pragma unroll
        for (int it = 0; it < 4; it++) {
            int idx = tid + it * 256;
            int j = idx >> 4, c4g = idx & 15;
            sVv[j * 17 + c4g] = vreg[it];
        }
        __syncthreads();

        // prefetch next K
        if (kt + 1 < 16) {
            const int k0n = (kt + 1) * 64;
            #pragma unroll
            for (int r = 0; r < 4; r++)
                kreg[r] = *(const float4*)&qbase[(size_t)(k0n + kj0 + r) * N3 + DH + kd4];
        }

        // ---- S = Q K^T ----
        float sf[8][4] = {};
        #pragma unroll
        for (int dg = 0; dg < 16; dg++) {
            const int pa = ty ^ dg;
            const int pb = tx ^ dg;
            #pragma unroll
            for (int dd = 0; dd < 4; dd++) {
                const int d = dg * 4 + dd;
                float4 a0 = sQtv[d * 32 + pa];
                float4 a1 = sQtv[d * 32 + 16 + pa];
                float4 b0 = sKtv[d * 16 + pb];
                float a[8] = {a0.x, a0.y, a0.z, a0.w, a1.x, a1.y, a1.z, a1.w};
                float bq[4] = {b0.x, b0.y, b0.z, b0.w};
                #pragma unroll
                for (int r = 0; r < 8; r++)
                    #pragma unroll
                    for (int c = 0; c < 4; c++)
                        sf[r][c] = fmaf(a[r], bq[c], sf[r][c]);
            }
        }

        // ---- online softmax (rows owned; 16-lane butterfly) ----
        #pragma unroll
        for (int r = 0; r < 8; r++) {
            const int qrow = (r < 4) ? (ty * 4 + r) : (64 + ty * 4 + r - 4);
            float mx = fmaxf(fmaxf(sf[r][0], sf[r][1]), fmaxf(sf[r][2], sf[r][3]));
            #pragma unroll
            for (int off = 8; off >= 1; off >>= 1)
                mx = fmaxf(mx, __shfl_xor_sync(0xffffffffu, mx, off));
            float m_new = fmaxf(m_i[r], mx);
            float p0 = __expf(sf[r][0] - m_new);
            float p1 = __expf(sf[r][1] - m_new);
            float p2 = __expf(sf[r][2] - m_new);
            float p3 = __expf(sf[r][3] - m_new);
            sPv[qrow * 17 + tx] = make_float4(p0, p1, p2, p3);
            float rs = (p0 + p1) + (p2 + p3);
            #pragma unroll
            for (int off = 8; off >= 1; off >>= 1)
                rs += __shfl_xor_sync(0xffffffffu, rs, off);
            float alpha = __expf(m_i[r] - m_new);
            l_i[r] = l_i[r] * alpha + rs;
            m_i[r] = m_new;
            #pragma unroll
            for (int c = 0; c < 4; c++) o[r][c] *= alpha;
        }
        __syncwarp();   // sP rows produced/consumed within the same warp

        // prefetch next V (latency hidden under PV)
        if (kt + 1 < 16) {
            const int k0n = (kt + 1) * 64;
            #pragma unroll
            for (int it = 0; it < 4; it++) {
                int idx = tid + it * 256;
                int j = idx >> 4, c4 = (idx & 15) << 2;
                vreg[it] = *(const float4*)&qbase[(size_t)(k0n + j) * N3 + 2 * DH + c4];
            }
        }

        // ---- O += P V ----
        #pragma unroll
        for (int j4 = 0; j4 < 16; j4++) {
            float4 b0 = sVv[(j4 * 4 + 0) * 17 + tx];
            float4 b1 = sVv[(j4 * 4 + 1) * 17 + tx];
            float4 b2 = sVv[(j4 * 4 + 2) * 17 + tx];
            float4 b3 = sVv[(j4 * 4 + 3) * 17 + tx];
            #pragma unroll
            for (int half = 0; half < 2; half++) {
                #pragma unroll
                for (int r = 0; r < 4; r++) {
                    float4 av = sPv[((half ? 64 : 0) + ty * 4 + r) * 17 + j4];
                    const int ro = half * 4 + r;
                    o[ro][0] = fmaf(av.x, b0.x, o[ro][0]);
                    o[ro][1] = fmaf(av.x, b0.y, o[ro][1]);
                    o[ro][2] = fmaf(av.x, b0.z, o[ro][2]);
                    o[ro][3] = fmaf(av.x, b0.w, o[ro][3]);
                    o[ro][0] = fmaf(av.y, b1.x, o[ro][0]);
                    o[ro][1] = fmaf(av.y, b1.y, o[ro][1]);
                    o[ro][2] = fmaf(av.y, b1.z, o[ro][2]);
                    o[ro][3] = fmaf(av.y, b1.w, o[ro][3]);
                    o[ro][0] = fmaf(av.z, b2.x, o[ro][0]);
                    o[ro][1] = fmaf(av.z, b2.y, o[ro][1]);
                    o[ro][2] = fmaf(av.z, b2.z, o[ro][2]);
                    o[ro][3] = fmaf(av.z, b2.w, o[ro][3]);
                    o[ro][0] = fmaf(av.w, b3.x, o[ro][0]);
                    o[ro][1] = fmaf(av.w, b3.y, o[ro][1]);
                    o[ro][2] = fmaf(av.w, b3.z, o[ro][2]);
                    o[ro][3] = fmaf(av.w, b3.w, o[ro][3]);
                }
            }
        }
    }

    float* rbase = g_res + ((size_t)b * SS + q0) * INNER + h * DH;
    #pragma unroll
    for (int r = 0; r < 8; r++) {
        const int qrow = (r < 4) ? (ty * 4 + r) : (64 + ty * 4 + r - 4);
        float inv = 1.f / l_i[r];
        float4 ov;
        ov.x = o[r][0] * inv; ov.y = o[r][1] * inv;
        ov.z = o[r][2] * inv; ov.w = o[r][3] * inv;
        *(float4*)&rbase[(size_t)qrow * INNER + tx * 4] = ov;
    }
}

// ---------------------------------------------------------------------------
// Kernel 3: out[b][c][s] = res @ W_out + b_out + x. 128x128 tile, 8x8 frag,
// double-buffered. Rows = c-dim so final writes are coalesced in s.
// ---------------------------------------------------------------------------
__global__ __launch_bounds__(256, 2) void out_gemm_k(
    const float* __restrict__ x, const float* __restrict__ Wo,
    const float* __restrict__ bo, float* __restrict__ out)
{
    __shared__ float sA[2][16][132];   // [buf][k][c]
    __shared__ float sB[2][16][132];   // [buf][k][s]
    const int s0 = blockIdx.x * 128;
    const int c0 = blockIdx.y * 128;
    const int b  = blockIdx.z;
    const int tid = threadIdx.x;
    const int tx = tid & 15, ty = tid >> 4;
    const int lk = tid >> 4, lc4 = (tid & 15) << 2;
    const int ls = tid >> 1, lkb = (tid & 1) << 3;

    float4 av0, av1, bv0, bv1;
    {
        const size_t arow = (size_t)lk * CC + c0 + lc4;
        av0 = *(const float4*)&Wo[arow];
        av1 = *(const float4*)&Wo[arow + 64];
        const size_t brow = ((size_t)(b * SS + s0 + ls)) * INNER + lkb;
        bv0 = *(const float4*)&g_res[brow];
        bv1 = *(const float4*)&g_res[brow + 4];
    }
    *(float4*)&sA[0][lk][lc4]      = av0;
    *(float4*)&sA[0][lk][lc4 + 64] = av1;
    sB[0][lkb + 0][ls] = bv0.x; sB[0][lkb + 1][ls] = bv0.y;
    sB[0][lkb + 2][ls] = bv0.z; sB[0][lkb + 3][ls] = bv0.w;
    sB[0][lkb + 4][ls] = bv1.x; sB[0][lkb + 5][ls] = bv1.y;
    sB[0][lkb + 6][ls] = bv1.z; sB[0][lkb + 7][ls] = bv1.w;
    __syncthreads();

    float acc[8][8] = {};
    for (int k0 = 0; k0 < INNER; k0 += 16) {
        const int buf = (k0 >> 4) & 1;
        const bool more = (k0 + 16) < INNER;
        if (more) {
            const size_t arow = (size_t)(k0 + 16 + lk) * CC + c0 + lc4;
            av0 = *(const float4*)&Wo[arow];
            av1 = *(const float4*)&Wo[arow + 64];
            const size_t brow = ((size_t)(b * SS + s0 + ls)) * INNER + k0 + 16 + lkb;
            bv0 = *(const float4*)&g_res[brow];
            bv1 = *(const float4*)&g_res[brow + 4];
        }
        #pragma unroll
        for (int k = 0; k < 16; k++) {
            float a[8], bq[8];
            #pragma unroll
            for (int r = 0; r < 4; r++) {
                a[r]      = sA[buf][k][ty * 4 + r];
                a[r + 4]  = sA[buf][k][64 + ty * 4 + r];
                bq[r]     = sB[buf][k][tx * 4 + r];
                bq[r + 4] = sB[buf][k][64 + tx * 4 + r];
            }
            #pragma unroll
            for (int r = 0; r < 8; r++)
                #pragma unroll
                for (int c = 0; c < 8; c++)
                    acc[r][c] = fmaf(a[r], bq[c], acc[r][c]);
        }
        if (more) {
            const int nb = buf ^ 1;
            *(float4*)&sA[nb][lk][lc4]      = av0;
            *(float4*)&sA[nb][lk][lc4 + 64] = av1;
            sB[nb][lkb + 0][ls] = bv0.x; sB[nb][lkb + 1][ls] = bv0.y;
            sB[nb][lkb + 2][ls] = bv0.z; sB[nb][lkb + 3][ls] = bv0.w;
            sB[nb][lkb + 4][ls] = bv1.x; sB[nb][lkb + 5][ls] = bv1.y;
            sB[nb][lkb + 6][ls] = bv1.z; sB[nb][lkb + 7][ls] = bv1.w;
            __syncthreads();
        }
    }

    #pragma unroll
    for (int r = 0; r < 8; r++) {
        const int c = c0 + ((r < 4) ? (ty * 4 + r) : (64 + ty * 4 + r - 4));
        const float bias = bo[c];
        const size_t base = ((size_t)(b * CC + c)) * SS + s0 + tx * 4;
        float4 xv0 = *(const float4*)&x[base];
        float4 xv1 = *(const float4*)&x[base + 64];
        float4 o0, o1;
        o0.x = acc[r][0] + bias + xv0.x; o0.y = acc[r][1] + bias + xv0.y;
        o0.z = acc[r][2] + bias + xv0.z; o0.w = acc[r][3] + bias + xv0.w;
        o1.x = acc[r][4] + bias + xv1.x; o1.y = acc[r][5] + bias + xv1.y;
        o1.z = acc[r][6] + bias + xv1.z; o1.w = acc[r][7] + bias + xv1.w;
        *(float4*)&out[base] = o0;
        *(float4*)&out[base + 64] = o1;
    }
}

// ---------------------------------------------------------------------------
extern "C" void kernel_launch(void* const* d_in, const int* in_sizes, int n_in,
                              void* d_out, int out_size)
{
    const float* x  = (const float*)d_in[0];
    const float* Wp = (const float*)d_in[1];
    const float* bp = (const float*)d_in[2];
    const float* Wo = (const float*)d_in[3];
    const float* bo = (const float*)d_in[4];
    float* out = (float*)d_out;

    const int attn_smem = (64 * 128 + 64 * 64 + 64 * 68 + 128 * 68) * 4; // 101376
    cudaFuncSetAttribute(attn_k, cudaFuncAttributeMaxDynamicSharedMemorySize,
                         attn_smem);

    dim3 g1(N3 / 128, (BB * SS) / 128);        // 12 x 128
    qkv_gemm_k<<<g1, 256>>>(x, Wp, bp);

    dim3 g2(SS / 128, BB * HEADS);             // 8 x 128
    attn_k<<<g2, 256, attn_smem>>>();

    dim3 g3(SS / 128, CC / 128, BB);           // 8 x 4 x 16
    out_gemm_k<<<g3, 256>>>(x, Wo, bo, out);
}

// round 6
// speedup vs baseline: 1.5509x; 1.3239x over previous
#include <cuda_runtime.h>

#define BB     16
#define CC     512
#define SS     1024
#define HEADS  8
#define DH     64
#define INNER  512     // HEADS*DH
#define N3     1536    // 3*INNER
#define ATT_SCALE 0.125f  // 64^-0.5

// Scratch (static device globals — allocation-free per harness rules)
__device__ float g_qkv[(size_t)BB * SS * N3];    // [b][s][h*192 + {q,k,v}]
__device__ float g_res[(size_t)BB * SS * INNER]; // [b][s][h*64+d]

// tf32 round-to-nearest (keeps value in a float container)
__device__ __forceinline__ float tf32r(float f) {
    unsigned u;
    asm("cvt.rna.tf32.f32 %0, %1;" : "=r"(u) : "f"(f));
    return __uint_as_float(u);
}
__device__ __forceinline__ float4 tf32r4(float4 v) {
    return make_float4(tf32r(v.x), tf32r(v.y), tf32r(v.z), tf32r(v.w));
}

// m16n8k8 tf32 MMA, fp32 accumulate (D == C)
__device__ __forceinline__ void mma_tf32(float* d, const float* a, const float* b) {
    asm volatile(
        "mma.sync.aligned.m16n8k8.row.col.f32.tf32.tf32.f32 "
        "{%0,%1,%2,%3}, {%4,%5,%6,%7}, {%8,%9}, {%0,%1,%2,%3};\n"
        : "+f"(d[0]), "+f"(d[1]), "+f"(d[2]), "+f"(d[3])
        : "r"(__float_as_uint(a[0])), "r"(__float_as_uint(a[1])),
          "r"(__float_as_uint(a[2])), "r"(__float_as_uint(a[3])),
          "r"(__float_as_uint(b[0])), "r"(__float_as_uint(b[1])));
}

// ---------------------------------------------------------------------------
// Kernel 1: qkv = xs @ W_proj + b_proj, xs[b][s][c] = x[b][c][s]
// 128x128 block tile, tf32 mma.sync, warp tile 64x32, double-buffered smem.
// ---------------------------------------------------------------------------
__global__ __launch_bounds__(256, 2) void qkv_gemm_k(
    const float* __restrict__ x, const float* __restrict__ Wp,
    const float* __restrict__ bp)
{
    __shared__ float sA[2][16][132];   // [buf][k][m]  (tf32-rounded)
    __shared__ float sB[2][16][132];   // [buf][k][n]  (tf32-rounded)
    const int n0 = blockIdx.x * 128;
    const int m0 = blockIdx.y * 128;
    const int b  = m0 >> 10;
    const int s0 = m0 & (SS - 1);
    const int tid = threadIdx.x;
    const int lk = tid >> 4, lm4 = (tid & 15) << 2;
    const int warp = tid >> 5, lane = tid & 31;
    const int wm = warp & 1, wn = warp >> 1;       // 2 x 4 warp grid
    const int gid = lane >> 2, tig = lane & 3;

    float4 av0, av1, bv0, bv1;
    {
        const size_t arow = ((size_t)(b * CC + lk)) * SS + s0 + lm4;
        const size_t brow = (size_t)lk * N3 + n0 + lm4;
        av0 = *(const float4*)&x[arow];
        av1 = *(const float4*)&x[arow + 64];
        bv0 = *(const float4*)&Wp[brow];
        bv1 = *(const float4*)&Wp[brow + 64];
    }
    *(float4*)&sA[0][lk][lm4]      = tf32r4(av0);
    *(float4*)&sA[0][lk][lm4 + 64] = tf32r4(av1);
    *(float4*)&sB[0][lk][lm4]      = tf32r4(bv0);
    *(float4*)&sB[0][lk][lm4 + 64] = tf32r4(bv1);
    __syncthreads();

    float acc[4][4][4] = {};   // [mf][nf][reg]

    for (int k0 = 0; k0 < CC; k0 += 16) {
        const int buf = (k0 >> 4) & 1;
        const bool more = (k0 + 16) < CC;
        if (more) {
            const size_t arow = ((size_t)(b * CC + k0 + 16 + lk)) * SS + s0 + lm4;
            const size_t brow = (size_t)(k0 + 16 + lk) * N3 + n0 + lm4;
            av0 = *(const float4*)&x[arow];
            av1 = *(const float4*)&x[arow + 64];
            bv0 = *(const float4*)&Wp[brow];
            bv1 = *(const float4*)&Wp[brow + 64];
        }
        #pragma unroll
        for (int ks = 0; ks < 16; ks += 8) {
            float afr[4][4], bfr[4][2];
            #pragma unroll
            for (int mf = 0; mf < 4; mf++) {
                const int m = wm * 64 + mf * 16 + gid;
                afr[mf][0] = sA[buf][ks + tig][m];
                afr[mf][1] = sA[buf][ks + tig][m + 8];
                afr[mf][2] = sA[buf][ks + tig + 4][m];
                afr[mf][3] = sA[buf][ks + tig + 4][m + 8];
            }
            #pragma unroll
            for (int nf = 0; nf < 4; nf++) {
                const int n = wn * 32 + nf * 8 + gid;
                bfr[nf][0] = sB[buf][ks + tig][n];
                bfr[nf][1] = sB[buf][ks + tig + 4][n];
            }
            #pragma unroll
            for (int mf = 0; mf < 4; mf++)
                #pragma unroll
                for (int nf = 0; nf < 4; nf++)
                    mma_tf32(acc[mf][nf], afr[mf], bfr[nf]);
        }
        if (more) {
            const int nb = buf ^ 1;
            *(float4*)&sA[nb][lk][lm4]      = tf32r4(av0);
            *(float4*)&sA[nb][lk][lm4 + 64] = tf32r4(av1);
            *(float4*)&sB[nb][lk][lm4]      = tf32r4(bv0);
            *(float4*)&sB[nb][lk][lm4 + 64] = tf32r4(bv1);
            __syncthreads();
        }
    }

    #pragma unroll
    for (int mf = 0; mf < 4; mf++) {
        const int rowa = m0 + wm * 64 + mf * 16 + gid;
        const int rowb = rowa + 8;
        #pragma unroll
        for (int nf = 0; nf < 4; nf++) {
            const int col = n0 + wn * 32 + nf * 8 + tig * 2;
            const float2 bias = *(const float2*)&bp[col];
            float2 oa = make_float2(acc[mf][nf][0] + bias.x, acc[mf][nf][1] + bias.y);
            float2 ob = make_float2(acc[mf][nf][2] + bias.x, acc[mf][nf][3] + bias.y);
            *(float2*)&g_qkv[(size_t)rowa * N3 + col] = oa;
            *(float2*)&g_qkv[(size_t)rowb * N3 + col] = ob;
        }
    }
}

// ---------------------------------------------------------------------------
// Kernel 2: flash attention (fp32, unchanged from R5).
// ---------------------------------------------------------------------------
__global__ __launch_bounds__(256, 2) void attn_k()
{
    extern __shared__ float sm[];
    float* sQt = sm;                  // [64][128] Q^T (scaled, swizzled)
    float* sKt = sQt + 64 * 128;      // [64][64]  K^T (swizzled)
    float* sV  = sKt + 64 * 64;       // [64][68]
    float* sP  = sV + 64 * 68;        // [128][68]
    float4* sQtv = (float4*)sQt;      // row stride 32
    float4* sKtv = (float4*)sKt;      // row stride 16
    float4* sVv  = (float4*)sV;       // row stride 17
    float4* sPv  = (float4*)sP;       // row stride 17

    const int bh = blockIdx.y;
    const int b = bh >> 3, h = bh & 7;
    const int q0 = blockIdx.x * 128;
    const int tid = threadIdx.x;
    const int tx = tid & 15, ty = tid >> 4;

    const float* qbase = g_qkv + (size_t)b * SS * N3 + h * (3 * DH);

    #pragma unroll
    for (int it = 0; it < 2; it++) {
        int idx = tid + it * 256;
        int d4g = idx & 15, rg = idx >> 4;
        int d4 = d4g << 2, i0 = rg << 2;
        float4 m0 = *(const float4*)&qbase[(size_t)(q0 + i0 + 0) * N3 + d4];
        float4 m1 = *(const float4*)&qbase[(size_t)(q0 + i0 + 1) * N3 + d4];
        float4 m2 = *(const float4*)&qbase[(size_t)(q0 + i0 + 2) * N3 + d4];
        float4 m3 = *(const float4*)&qbase[(size_t)(q0 + i0 + 3) * N3 + d4];
        int phys = (rg & 16) | ((rg & 15) ^ d4g);
        sQtv[(d4 + 0) * 32 + phys] = make_float4(m0.x * ATT_SCALE, m1.x * ATT_SCALE,
                                                 m2.x * ATT_SCALE, m3.x * ATT_SCALE);
        sQtv[(d4 + 1) * 32 + phys] = make_float4(m0.y * ATT_SCALE, m1.y * ATT_SCALE,
                                                 m2.y * ATT_SCALE, m3.y * ATT_SCALE);
        sQtv[(d4 + 2) * 32 + phys] = make_float4(m0.z * ATT_SCALE, m1.z * ATT_SCALE,
                                                 m2.z * ATT_SCALE, m3.z * ATT_SCALE);
        sQtv[(d4 + 3) * 32 + phys] = make_float4(m0.w * ATT_SCALE, m1.w * ATT_SCALE,
                                                 m2.w * ATT_SCALE, m3.w * ATT_SCALE);
    }

    float m_i[8], l_i[8], o[8][4] = {};
    #pragma unroll
    for (int r = 0; r < 8; r++) { m_i[r] = -1e30f; l_i[r] = 0.f; }

    const int kd4g = tid & 15, krg = tid >> 4;
    const int kd4 = kd4g << 2, kj0 = krg << 2;
    const int kphys = krg ^ kd4g;

    float4 kreg[4], vreg[4];
    #pragma unroll
    for (int r = 0; r < 4; r++)
        kreg[r] = *(const float4*)&qbase[(size_t)(kj0 + r) * N3 + DH + kd4];
    #pragma unroll
    for (int it = 0; it < 4; it++) {
        int idx = tid + it * 256;
        int j = idx >> 4, c4 = (idx & 15) << 2;
        vreg[it] = *(const float4*)&qbase[(size_t)j * N3 + 2 * DH + c4];
    }

    for (int kt = 0; kt < 16; kt++) {
        __syncthreads();
        sKtv[(kd4 + 0) * 16 + kphys] = make_float4(kreg[0].x, kreg[1].x, kreg[2].x, kreg[3].x);
        sKtv[(kd4 + 1) * 16 + kphys] = make_float4(kreg[0].y, kreg[1].y, kreg[2].y, kreg[3].y);
        sKtv[(kd4 + 2) * 16 + kphys] = make_float4(kreg[0].z, kreg[1].z, kreg[2].z, kreg[3].z);
        sKtv[(kd4 + 3) * 16 + kphys] = make_float4(kreg[0].w, kreg[1].w, kreg[2].w, kreg[3].w);
        #pragma unroll
        for (int it = 0; it < 4; it++) {
            int idx = tid + it * 256;
            int j = idx >> 4, c4g = idx & 15;
            sVv[j * 17 + c4g] = vreg[it];
        }
        __syncthreads();

        if (kt + 1 < 16) {
            const int k0n = (kt + 1) * 64;
            #pragma unroll
            for (int r = 0; r < 4; r++)
                kreg[r] = *(const float4*)&qbase[(size_t)(k0n + kj0 + r) * N3 + DH + kd4];
        }

        float sf[8][4] = {};
        #pragma unroll
        for (int dg = 0; dg < 16; dg++) {
            const int pa = ty ^ dg;
            const int pb = tx ^ dg;
            #pragma unroll
            for (int dd = 0; dd < 4; dd++) {
                const int d = dg * 4 + dd;
                float4 a0 = sQtv[d * 32 + pa];
                float4 a1 = sQtv[d * 32 + 16 + pa];
                float4 b0 = sKtv[d * 16 + pb];
                float a[8] = {a0.x, a0.y, a0.z, a0.w, a1.x, a1.y, a1.z, a1.w};
                float bq[4] = {b0.x, b0.y, b0.z, b0.w};
                #pragma unroll
                for (int r = 0; r < 8; r++)
                    #pragma unroll
                    for (int c = 0; c < 4; c++)
                        sf[r][c] = fmaf(a[r], bq[c], sf[r][c]);
            }
        }

        #pragma unroll
        for (int r = 0; r < 8; r++) {
            const int qrow = (r < 4) ? (ty * 4 + r) : (64 + ty * 4 + r - 4);
            float mx = fmaxf(fmaxf(sf[r][0], sf[r][1]), fmaxf(sf[r][2], sf[r][3]));
            #pragma unroll
            for (int off = 8; off >= 1; off >>= 1)
                mx = fmaxf(mx, __shfl_xor_sync(0xffffffffu, mx, off));
            float m_new = fmaxf(m_i[r], mx);
            float p0 = __expf(sf[r][0] - m_new);
            float p1 = __expf(sf[r][1] - m_new);
            float p2 = __expf(sf[r][2] - m_new);
            float p3 = __expf(sf[r][3] - m_new);
            sPv[qrow * 17 + tx] = make_float4(p0, p1, p2, p3);
            float rs = (p0 + p1) + (p2 + p3);
            #pragma unroll
            for (int off = 8; off >= 1; off >>= 1)
                rs += __shfl_xor_sync(0xffffffffu, rs, off);
            float alpha = __expf(m_i[r] - m_new);
            l_i[r] = l_i[r] * alpha + rs;
            m_i[r] = m_new;
            #pragma unroll
            for (int c = 0; c < 4; c++) o[r][c] *= alpha;
        }
        __syncwarp();

        if (kt + 1 < 16) {
            const int k0n = (kt + 1) * 64;
            #pragma unroll
            for (int it = 0; it < 4; it++) {
                int idx = tid + it * 256;
                int j = idx >> 4, c4 = (idx & 15) << 2;
                vreg[it] = *(const float4*)&qbase[(size_t)(k0n + j) * N3 + 2 * DH + c4];
            }
        }

        #pragma unroll
        for (int j4 = 0; j4 < 16; j4++) {
            float4 b0 = sVv[(j4 * 4 + 0) * 17 + tx];
            float4 b1 = sVv[(j4 * 4 + 1) * 17 + tx];
            float4 b2 = sVv[(j4 * 4 + 2) * 17 + tx];
            float4 b3 = sVv[(j4 * 4 + 3) * 17 + tx];
            #pragma unroll
            for (int half = 0; half < 2; half++) {
                #pragma unroll
                for (int r = 0; r < 4; r++) {
                    float4 av = sPv[((half ? 64 : 0) + ty * 4 + r) * 17 + j4];
                    const int ro = half * 4 + r;
                    o[ro][0] = fmaf(av.x, b0.x, o[ro][0]);
                    o[ro][1] = fmaf(av.x, b0.y, o[ro][1]);
                    o[ro][2] = fmaf(av.x, b0.z, o[ro][2]);
                    o[ro][3] = fmaf(av.x, b0.w, o[ro][3]);
                    o[ro][0] = fmaf(av.y, b1.x, o[ro][0]);
                    o[ro][1] = fmaf(av.y, b1.y, o[ro][1]);
                    o[ro][2] = fmaf(av.y, b1.z, o[ro][2]);
                    o[ro][3] = fmaf(av.y, b1.w, o[ro][3]);
                    o[ro][0] = fmaf(av.z, b2.x, o[ro][0]);
                    o[ro][1] = fmaf(av.z, b2.y, o[ro][1]);
                    o[ro][2] = fmaf(av.z, b2.z, o[ro][2]);
                    o[ro][3] = fmaf(av.z, b2.w, o[ro][3]);
                    o[ro][0] = fmaf(av.w, b3.x, o[ro][0]);
                    o[ro][1] = fmaf(av.w, b3.y, o[ro][1]);
                    o[ro][2] = fmaf(av.w, b3.z, o[ro][2]);
                    o[ro][3] = fmaf(av.w, b3.w, o[ro][3]);
                }
            }
        }
    }

    float* rbase = g_res + ((size_t)b * SS + q0) * INNER + h * DH;
    #pragma unroll
    for (int r = 0; r < 8; r++) {
        const int qrow = (r < 4) ? (ty * 4 + r) : (64 + ty * 4 + r - 4);
        float inv = 1.f / l_i[r];
        float4 ov;
        ov.x = o[r][0] * inv; ov.y = o[r][1] * inv;
        ov.z = o[r][2] * inv; ov.w = o[r][3] * inv;
        *(float4*)&rbase[(size_t)qrow * INNER + tx * 4] = ov;
    }
}

// ---------------------------------------------------------------------------
// Kernel 3: out[b][c][s] = res @ W_out + b_out + x. tf32 mma.sync,
// 128(c) x 128(s) block tile, warp tile 64x32, double-buffered.
// ---------------------------------------------------------------------------
__global__ __launch_bounds__(256, 2) void out_gemm_k(
    const float* __restrict__ x, const float* __restrict__ Wo,
    const float* __restrict__ bo, float* __restrict__ out)
{
    __shared__ float sA[2][16][132];   // [buf][k][c]  (tf32)
    __shared__ float sB[2][16][132];   // [buf][k][s]  (tf32)
    const int s0 = blockIdx.x * 128;
    const int c0 = blockIdx.y * 128;
    const int b  = blockIdx.z;
    const int tid = threadIdx.x;
    const int lk = tid >> 4, lc4 = (tid & 15) << 2;
    const int ls = tid >> 1, lkb = (tid & 1) << 3;
    const int warp = tid >> 5, lane = tid & 31;
    const int wm = warp & 1, wn = warp >> 1;
    const int gid = lane >> 2, tig = lane & 3;

    float4 av0, av1, bv0, bv1;
    {
        const size_t arow = (size_t)lk * CC + c0 + lc4;
        av0 = *(const float4*)&Wo[arow];
        av1 = *(const float4*)&Wo[arow + 64];
        const size_t brow = ((size_t)(b * SS + s0 + ls)) * INNER + lkb;
        bv0 = *(const float4*)&g_res[brow];
        bv1 = *(const float4*)&g_res[brow + 4];
    }
    *(float4*)&sA[0][lk][lc4]      = tf32r4(av0);
    *(float4*)&sA[0][lk][lc4 + 64] = tf32r4(av1);
    sB[0][lkb + 0][ls] = tf32r(bv0.x); sB[0][lkb + 1][ls] = tf32r(bv0.y);
    sB[0][lkb + 2][ls] = tf32r(bv0.z); sB[0][lkb + 3][ls] = tf32r(bv0.w);
    sB[0][lkb + 4][ls] = tf32r(bv1.x); sB[0][lkb + 5][ls] = tf32r(bv1.y);
    sB[0][lkb + 6][ls] = tf32r(bv1.z); sB[0][lkb + 7][ls] = tf32r(bv1.w);
    __syncthreads();

    float acc[4][4][4] = {};

    for (int k0 = 0; k0 < INNER; k0 += 16) {
        const int buf = (k0 >> 4) & 1;
        const bool more = (k0 + 16) < INNER;
        if (more) {
            const size_t arow = (size_t)(k0 + 16 + lk) * CC + c0 + lc4;
            av0 = *(const float4*)&Wo[arow];
            av1 = *(const float4*)&Wo[arow + 64];
            const size_t brow = ((size_t)(b * SS + s0 + ls)) * INNER + k0 + 16 + lkb;
            bv0 = *(const float4*)&g_res[brow];
            bv1 = *(const float4*)&g_res[brow + 4];
        }
        #pragma unroll
        for (int ks = 0; ks < 16; ks += 8) {
            float afr[4][4], bfr[4][2];
            #pragma unroll
            for (int mf = 0; mf < 4; mf++) {
                const int m = wm * 64 + mf * 16 + gid;
                afr[mf][0] = sA[buf][ks + tig][m];
                afr[mf][1] = sA[buf][ks + tig][m + 8];
                afr[mf][2] = sA[buf][ks + tig + 4][m];
                afr[mf][3] = sA[buf][ks + tig + 4][m + 8];
            }
            #pragma unroll
            for (int nf = 0; nf < 4; nf++) {
                const int n = wn * 32 + nf * 8 + gid;
                bfr[nf][0] = sB[buf][ks + tig][n];
                bfr[nf][1] = sB[buf][ks + tig + 4][n];
            }
            #pragma unroll
            for (int mf = 0; mf < 4; mf++)
                #pragma unroll
                for (int nf = 0; nf < 4; nf++)
                    mma_tf32(acc[mf][nf], afr[mf], bfr[nf]);
        }
        if (more) {
            const int nb = buf ^ 1;
            *(float4*)&sA[nb][lk][lc4]      = tf32r4(av0);
            *(float4*)&sA[nb][lk][lc4 + 64] = tf32r4(av1);
            sB[nb][lkb + 0][ls] = tf32r(bv0.x); sB[nb][lkb + 1][ls] = tf32r(bv0.y);
            sB[nb][lkb + 2][ls] = tf32r(bv0.z); sB[nb][lkb + 3][ls] = tf32r(bv0.w);
            sB[nb][lkb + 4][ls] = tf32r(bv1.x); sB[nb][lkb + 5][ls] = tf32r(bv1.y);
            sB[nb][lkb + 6][ls] = tf32r(bv1.z); sB[nb][lkb + 7][ls] = tf32r(bv1.w);
            __syncthreads();
        }
    }

    #pragma unroll
    for (int mf = 0; mf < 4; mf++) {
        const int ca = c0 + wm * 64 + mf * 16 + gid;
        const int cb = ca + 8;
        const float biasa = bo[ca];
        const float biasb = bo[cb];
        #pragma unroll
        for (int nf = 0; nf < 4; nf++) {
            const int s = s0 + wn * 32 + nf * 8 + tig * 2;
            const size_t basea = ((size_t)(b * CC + ca)) * SS + s;
            const size_t baseb = ((size_t)(b * CC + cb)) * SS + s;
            float2 xva = *(const float2*)&x[basea];
            float2 xvb = *(const float2*)&x[baseb];
            float2 oa = make_float2(acc[mf][nf][0] + biasa + xva.x,
                                    acc[mf][nf][1] + biasa + xva.y);
            float2 ob = make_float2(acc[mf][nf][2] + biasb + xvb.x,
                                    acc[mf][nf][3] + biasb + xvb.y);
            *(float2*)&out[basea] = oa;
            *(float2*)&out[baseb] = ob;
        }
    }
}

// ---------------------------------------------------------------------------
extern "C" void kernel_launch(void* const* d_in, const int* in_sizes, int n_in,
                              void* d_out, int out_size)
{
    const float* x  = (const float*)d_in[0];
    const float* Wp = (const float*)d_in[1];
    const float* bp = (const float*)d_in[2];
    const float* Wo = (const float*)d_in[3];
    const float* bo = (const float*)d_in[4];
    float* out = (float*)d_out;

    const int attn_smem = (64 * 128 + 64 * 64 + 64 * 68 + 128 * 68) * 4; // 101376
    cudaFuncSetAttribute(attn_k, cudaFuncAttributeMaxDynamicSharedMemorySize,
                         attn_smem);

    dim3 g1(N3 / 128, (BB * SS) / 128);        // 12 x 128
    qkv_gemm_k<<<g1, 256>>>(x, Wp, bp);

    dim3 g2(SS / 128, BB * HEADS);             // 8 x 128
    attn_k<<<g2, 256, attn_smem>>>();

    dim3 g3(SS / 128, CC / 128, BB);           // 8 x 4 x 16
    out_gemm_k<<<g3, 256>>>(x, Wo, bo, out);
}